// round 8
// baseline (speedup 1.0000x reference)
#include <cuda_runtime.h>
#include <math.h>
#include <stdint.h>

#define NN 100000
#define EE 1600000
#define F_IN 256
#define DIM  32
#define NC   40

// ---------------- scratch (device globals) -----------------------------------
__device__ __align__(256) float g_y[(NN + 1) * DIM];
__device__ __align__(256) float g_r[(NN + 1) * DIM];
__device__ __align__(256) float g_h[(NN + 1) * DIM];
__device__ __align__(256) float g_invdeg[NN];
__device__ __align__(256) int   g_degi[NN];
__device__ __align__(256) int   g_rowptr[NN];
__device__ __align__(256) int   g_cur[NN];
__device__ __align__(256) int   g_csr[EE];
__device__ __align__(256) int   g_blksum[128];
__device__ int g_shift;   // 1 if edge_index is int64, 0 if int32

// ---------------- packed f32x2 helpers ----------------------------------------
__device__ __forceinline__ unsigned long long pack2(float a, float b) {
    unsigned long long d;
    asm("mov.b64 %0, {%1,%2};" : "=l"(d) : "f"(a), "f"(b));
    return d;
}
__device__ __forceinline__ void unpack2(unsigned long long d, float& a, float& b) {
    asm("mov.b64 {%0,%1}, %2;" : "=f"(a), "=f"(b) : "l"(d));
}
__device__ __forceinline__ void fma2(unsigned long long& d,
                                     unsigned long long a, unsigned long long b) {
    asm("fma.rn.f32x2 %0, %1, %2, %0;" : "+l"(d) : "l"(a), "l"(b));
}
__device__ __forceinline__ int clampN(int v, int N) {
    return min(max(v, 0), N - 1);
}
__device__ __forceinline__ int edge_get(const int* __restrict__ w, int E,
                                        int which, int e, int shift, int N) {
    int v = w[(size_t)((size_t)which * E + e) << shift];
    return clampN(v, N);
}

// ---------------- k_zero: deg=0, zero-row init, dtype detect ------------------
__global__ void k_zero(const int* __restrict__ w, int N) {
    int i = blockIdx.x * blockDim.x + threadIdx.x;
    if (i < N) g_degi[i] = 0;
    if (i < DIM) { g_y[(size_t)N * DIM + i] = 0.f; g_h[(size_t)N * DIM + i] = 0.f; }
    if (blockIdx.x == 0) {
        __shared__ int any_nz;
        if (threadIdx.x == 0) any_nz = 0;
        __syncthreads();
        int nz = 0;
        #pragma unroll
        for (int j = 0; j < 8; ++j)
            nz |= w[2 * (threadIdx.x * 8 + j) + 1];
        if (nz) atomicOr(&any_nz, 1);
        __syncthreads();
        if (threadIdx.x == 0) g_shift = any_nz ? 0 : 1;
    }
}

// ---------------- k_deg: 4 edges/thread, vectorized dst reads -----------------
__global__ void k_deg(const int* __restrict__ w, int E, int N) {
    int e = (blockIdx.x * blockDim.x + threadIdx.x) * 4;
    if (e >= E) return;
    int shift = g_shift;
    if (e + 4 <= E) {
        int d0, d1, d2, d3;
        if (shift) {
            const int4* p = (const int4*)(w + (((size_t)E + e) << 1));
            int4 a = p[0], b = p[1];
            d0 = a.x; d1 = a.z; d2 = b.x; d3 = b.z;
        } else {
            int4 a = *(const int4*)(w + (size_t)E + e);
            d0 = a.x; d1 = a.y; d2 = a.z; d3 = a.w;
        }
        atomicAdd(&g_degi[clampN(d0, N)], 1);
        atomicAdd(&g_degi[clampN(d1, N)], 1);
        atomicAdd(&g_degi[clampN(d2, N)], 1);
        atomicAdd(&g_degi[clampN(d3, N)], 1);
    } else {
        for (int k = e; k < E; ++k)
            atomicAdd(&g_degi[edge_get(w, E, 1, k, shift, N)], 1);
    }
}

// ---------------- scanA ---------------------------------------------------------
__global__ void __launch_bounds__(1024) k_scanA(int N) {
    __shared__ int wsum[32];
    int t = threadIdx.x, i = blockIdx.x * 1024 + t;
    int lane = t & 31, w = t >> 5;
    int v = (i < N) ? g_degi[i] : 0;
    int inc = v;
    #pragma unroll
    for (int o = 1; o < 32; o <<= 1) {
        int u = __shfl_up_sync(0xffffffffu, inc, o);
        if (lane >= o) inc += u;
    }
    if (lane == 31) wsum[w] = inc;
    __syncthreads();
    if (w == 0) {
        int s = wsum[lane], si = s;
        #pragma unroll
        for (int o = 1; o < 32; o <<= 1) {
            int u = __shfl_up_sync(0xffffffffu, si, o);
            if (lane >= o) si += u;
        }
        wsum[lane] = si - s;
        if (lane == 31) g_blksum[blockIdx.x] = si;
    }
    __syncthreads();
    if (i < N) g_rowptr[i] = inc - v + wsum[w];
}

// ---------------- scanC (absorbs scanB) -----------------------------------------
__global__ void __launch_bounds__(256) k_scanC(int N, int nb) {
    __shared__ int sp0, sb0;
    int i0 = blockIdx.x * 256;
    int b0 = i0 >> 10;
    if (threadIdx.x < 32) {
        int lane = threadIdx.x;
        int s = 0;
        for (int j = lane; j < b0; j += 32) s += g_blksum[j];
        #pragma unroll
        for (int o = 16; o; o >>= 1) s += __shfl_xor_sync(0xffffffffu, s, o);
        if (lane == 0) { sp0 = s; sb0 = (b0 + 1 < nb) ? g_blksum[b0] : 0; }
    }
    __syncthreads();
    int i = i0 + threadIdx.x;
    if (i >= N) return;
    int off = ((i >> 10) == b0) ? sp0 : sp0 + sb0;
    int rp = g_rowptr[i] + off;
    g_rowptr[i] = rp;
    g_cur[i] = rp;
    g_invdeg[i] = 1.0f / fmaxf((float)g_degi[i], 1.0f);
}

// ---------------- k_fill: 4 edges/thread, vectorized -----------------------------
__global__ void k_fill(const int* __restrict__ w, int E, int N) {
    int e = (blockIdx.x * blockDim.x + threadIdx.x) * 4;
    if (e >= E) return;
    int shift = g_shift;
    if (e + 4 <= E) {
        int s0, s1, s2, s3, d0, d1, d2, d3;
        if (shift) {
            const int4* ps = (const int4*)(w + ((size_t)e << 1));
            const int4* pd = (const int4*)(w + (((size_t)E + e) << 1));
            int4 a0 = ps[0], a1 = ps[1], b0 = pd[0], b1 = pd[1];
            s0 = a0.x; s1 = a0.z; s2 = a1.x; s3 = a1.z;
            d0 = b0.x; d1 = b0.z; d2 = b1.x; d3 = b1.z;
        } else {
            int4 a = *(const int4*)(w + (size_t)e);
            int4 b = *(const int4*)(w + (size_t)E + e);
            s0 = a.x; s1 = a.y; s2 = a.z; s3 = a.w;
            d0 = b.x; d1 = b.y; d2 = b.z; d3 = b.w;
        }
        s0 = clampN(s0, N); s1 = clampN(s1, N);
        s2 = clampN(s2, N); s3 = clampN(s3, N);
        d0 = clampN(d0, N); d1 = clampN(d1, N);
        d2 = clampN(d2, N); d3 = clampN(d3, N);
        int p0 = atomicAdd(&g_cur[d0], 1); g_csr[min(p0, EE - 1)] = s0;
        int p1 = atomicAdd(&g_cur[d1], 1); g_csr[min(p1, EE - 1)] = s1;
        int p2 = atomicAdd(&g_cur[d2], 1); g_csr[min(p2, EE - 1)] = s2;
        int p3 = atomicAdd(&g_cur[d3], 1); g_csr[min(p3, EE - 1)] = s3;
    } else {
        for (int k = e; k < E; ++k) {
            int s = edge_get(w, E, 0, k, shift, N);
            int d = edge_get(w, E, 1, k, shift, N);
            int pos = atomicAdd(&g_cur[d], 1);
            g_csr[min(pos, EE - 1)] = s;
        }
    }
}

// ---------------- GEMM1: y = x@W1l, r = x@W1r ------------------------------------
// 256 threads, 8 warps, 128 rows/CTA (16 rows/warp), K in 4 quarters of 64.
// Per warp per k-quad: 2 LDS.128 (w, 8 wf) + 16 bc LDS.128 (x, 16 wf) + 64 FFMA2.
__global__ void __launch_bounds__(256) k_gemm1(const float* __restrict__ x,
                                               const float* __restrict__ W1l,
                                               const float* __restrict__ W1r,
                                               int N) {
    __shared__ ulonglong2 sW[16 * 2 * 32];    // [q][j][c] (wl01, wr01)   16 KB
    __shared__ ulonglong2 sX[128 * 16];       // [row][quad]              32 KB
    const int tid  = threadIdx.x;
    const int warp = tid >> 5;
    const int lane = tid & 31;
    const int row0 = blockIdx.x * 128;

    unsigned long long aL[16], aR[16];
    #pragma unroll
    for (int r = 0; r < 16; ++r) { aL[r] = 0ull; aR[r] = 0ull; }

    for (int quarter = 0; quarter < 4; ++quarter) {
        const int kbase = quarter * 64;
        if (quarter) __syncthreads();
        // stage weights: i = [q:4][j:1][c:5]
        #pragma unroll
        for (int it = 0; it < 4; ++it) {
            int i = tid + 256 * it;
            int c = i & 31, j = (i >> 5) & 1, q = i >> 6;
            int k = kbase + q * 4 + j * 2;
            sW[i] = make_ulonglong2(
                pack2(W1l[k * DIM + c], W1l[(k + 1) * DIM + c]),
                pack2(W1r[k * DIM + c], W1r[(k + 1) * DIM + c]));
        }
        // stage x: i = [row:7][quad:4], coalesced float4 loads
        #pragma unroll
        for (int it = 0; it < 8; ++it) {
            int i = tid + 256 * it;
            int quad = i & 15, row = i >> 4;
            int grow = min(row0 + row, N - 1);
            ((float4*)sX)[i] =
                *(const float4*)(x + (size_t)grow * F_IN + kbase + quad * 4);
        }
        __syncthreads();

        const ulonglong2* xrow = &sX[(warp * 16) * 16];
        #pragma unroll 2
        for (int q = 0; q < 16; ++q) {
            ulonglong2 w0 = sW[(q * 2 + 0) * 32 + lane];   // j=0: (wl01, wr01)
            ulonglong2 w1 = sW[(q * 2 + 1) * 32 + lane];   // j=1
            #pragma unroll
            for (int r = 0; r < 16; ++r) {
                ulonglong2 xv = xrow[r * 16 + q];          // broadcast, 16B quad
                fma2(aL[r], xv.x, w0.x);
                fma2(aR[r], xv.x, w0.y);
                fma2(aL[r], xv.y, w1.x);
                fma2(aR[r], xv.y, w1.y);
            }
        }
    }

    #pragma unroll
    for (int r = 0; r < 16; ++r) {
        int row = row0 + warp * 16 + r;
        if (row < N) {
            float e, o;
            unpack2(aL[r], e, o); g_y[(size_t)row * DIM + lane] = e + o;
            unpack2(aR[r], e, o); g_r[(size_t)row * DIM + lane] = e + o;
        }
    }
}

// ---------------- layer 1: gather(y) -> h = relu(agg*invd + r + b1) --------------
__global__ void __launch_bounds__(256) k_l1(const float* __restrict__ b1, int N) {
    int warp = threadIdx.x >> 5;
    int lane = threadIdx.x & 31;
    int n = blockIdx.x * 8 + warp;
    if (n >= N) return;

    int start = g_rowptr[n];
    int dn    = g_degi[n];
    int dnp   = (dn + 7) & ~7;
    float acc0 = 0.f, acc1 = 0.f;
    for (int j0 = 0; j0 < dnp; j0 += 32) {
        int m = min(32, dnp - j0);              // multiple of 8
        int idx = (j0 + lane < dn) ? g_csr[start + j0 + lane] : N;
        for (int k = 0; k < m; k += 8) {
            int s0 = __shfl_sync(0xffffffffu, idx, k);
            int s1 = __shfl_sync(0xffffffffu, idx, k + 1);
            int s2 = __shfl_sync(0xffffffffu, idx, k + 2);
            int s3 = __shfl_sync(0xffffffffu, idx, k + 3);
            int s4 = __shfl_sync(0xffffffffu, idx, k + 4);
            int s5 = __shfl_sync(0xffffffffu, idx, k + 5);
            int s6 = __shfl_sync(0xffffffffu, idx, k + 6);
            int s7 = __shfl_sync(0xffffffffu, idx, k + 7);
            float v0 = g_y[(size_t)s0 * DIM + lane];
            float v1 = g_y[(size_t)s1 * DIM + lane];
            float v2 = g_y[(size_t)s2 * DIM + lane];
            float v3 = g_y[(size_t)s3 * DIM + lane];
            float v4 = g_y[(size_t)s4 * DIM + lane];
            float v5 = g_y[(size_t)s5 * DIM + lane];
            float v6 = g_y[(size_t)s6 * DIM + lane];
            float v7 = g_y[(size_t)s7 * DIM + lane];
            acc0 += (v0 + v1) + (v2 + v3);
            acc1 += (v4 + v5) + (v6 + v7);
        }
    }
    float v = (acc0 + acc1) * g_invdeg[n] + g_r[(size_t)n * DIM + lane] + b1[lane];
    g_h[(size_t)n * DIM + lane] = fmaxf(v, 0.f);
}

// ---------------- layer 2 + log_softmax -------------------------------------------
__global__ void __launch_bounds__(256) k_out(const float* __restrict__ W2l,
                                             const float* __restrict__ W2r,
                                             const float* __restrict__ b2,
                                             float* __restrict__ out, int N) {
    __shared__ unsigned long long sW2[DIM * 64];
    for (int i = threadIdx.x; i < DIM * 64; i += 256) {
        int k = i >> 6, c = i & 63;
        float wl = (c < NC) ? W2l[k * NC + c] : 0.f;
        float wr = (c < NC) ? W2r[k * NC + c] : 0.f;
        sW2[i] = pack2(wl, wr);
    }
    __syncthreads();

    int warp = threadIdx.x >> 5;
    int lane = threadIdx.x & 31;
    int n = blockIdx.x * 8 + warp;
    if (n >= N) return;

    int start = g_rowptr[n];
    int dn    = g_degi[n];
    int dnp   = (dn + 7) & ~7;
    float acc0g = 0.f, acc1g = 0.f;
    for (int j0 = 0; j0 < dnp; j0 += 32) {
        int m = min(32, dnp - j0);
        int idx = (j0 + lane < dn) ? g_csr[start + j0 + lane] : N;
        for (int k = 0; k < m; k += 8) {
            int s0 = __shfl_sync(0xffffffffu, idx, k);
            int s1 = __shfl_sync(0xffffffffu, idx, k + 1);
            int s2 = __shfl_sync(0xffffffffu, idx, k + 2);
            int s3 = __shfl_sync(0xffffffffu, idx, k + 3);
            int s4 = __shfl_sync(0xffffffffu, idx, k + 4);
            int s5 = __shfl_sync(0xffffffffu, idx, k + 5);
            int s6 = __shfl_sync(0xffffffffu, idx, k + 6);
            int s7 = __shfl_sync(0xffffffffu, idx, k + 7);
            float v0 = g_h[(size_t)s0 * DIM + lane];
            float v1 = g_h[(size_t)s1 * DIM + lane];
            float v2 = g_h[(size_t)s2 * DIM + lane];
            float v3 = g_h[(size_t)s3 * DIM + lane];
            float v4 = g_h[(size_t)s4 * DIM + lane];
            float v5 = g_h[(size_t)s5 * DIM + lane];
            float v6 = g_h[(size_t)s6 * DIM + lane];
            float v7 = g_h[(size_t)s7 * DIM + lane];
            acc0g += (v0 + v1) + (v2 + v3);
            acc1g += (v4 + v5) + (v6 + v7);
        }
    }
    float a_l = (acc0g + acc1g) * g_invdeg[n];
    float h_l = g_h[(size_t)n * DIM + lane];

    unsigned long long p0 = 0ull, p1 = 0ull;
    #pragma unroll
    for (int k = 0; k < DIM; ++k) {
        float ak = __shfl_sync(0xffffffffu, a_l, k);
        float hk = __shfl_sync(0xffffffffu, h_l, k);
        unsigned long long ap = pack2(ak, hk);
        fma2(p0, ap, sW2[k * 64 + lane]);
        fma2(p1, ap, sW2[k * 64 + 32 + lane]);
    }
    float s0l, s0h, s1l, s1h;
    unpack2(p0, s0l, s0h);
    unpack2(p1, s1l, s1h);

    bool has1 = (lane < NC - 32);
    float acc0 = b2[lane] + s0l + s0h;
    float acc1 = (has1 ? b2[32 + lane] : 0.f) + s1l + s1h;

    float v1 = has1 ? acc1 : -INFINITY;
    float m = fmaxf(acc0, v1);
    #pragma unroll
    for (int o = 16; o; o >>= 1) m = fmaxf(m, __shfl_xor_sync(0xffffffffu, m, o));
    float s = expf(acc0 - m) + (has1 ? expf(acc1 - m) : 0.f);
    #pragma unroll
    for (int o = 16; o; o >>= 1) s += __shfl_xor_sync(0xffffffffu, s, o);
    float lse = m + logf(s);

    out[(size_t)n * NC + lane] = acc0 - lse;
    if (has1) out[(size_t)n * NC + 32 + lane] = acc1 - lse;
}

// ---------------- launch -----------------------------------------------------------
extern "C" void kernel_launch(void* const* d_in, const int* in_sizes, int n_in,
                              void* d_out, int out_size) {
    const float* x   = (const float*)d_in[0];
    const int*   ew  = (const int*)d_in[1];
    const float* W1l = (const float*)d_in[2];
    const float* W1r = (const float*)d_in[3];
    const float* b1  = (const float*)d_in[4];
    const float* W2l = (const float*)d_in[5];
    const float* W2r = (const float*)d_in[6];
    const float* b2  = (const float*)d_in[7];
    float*       out = (float*)d_out;

    const int N = in_sizes[0] / F_IN;   // 100000
    const int E = in_sizes[1] / 2;      // 1600000
    const int nb = (N + 1023) / 1024;

    k_zero <<<(N + 255) / 256, 256>>>(ew, N);
    k_deg  <<<(E / 4 + 255) / 256, 256>>>(ew, E, N);
    k_scanA<<<nb, 1024>>>(N);
    k_gemm1<<<(N + 127) / 128, 256>>>(x, W1l, W1r, N);   // 4th launch: ncu window
    k_scanC<<<(N + 255) / 256, 256>>>(N, nb);
    k_fill <<<(E / 4 + 255) / 256, 256>>>(ew, E, N);
    k_l1   <<<(N + 7) / 8, 256>>>(b1, N);
    k_out  <<<(N + 7) / 8, 256>>>(W2l, W2r, b2, out, N);
}